// round 16
// baseline (speedup 1.0000x reference)
#include <cuda_runtime.h>

// SSIM loss, fused separable 11x11 Gaussian, B=16 C=3 H=512 W=512 fp32.
// v16 = v15 + ring ROTATION-BY-UNROLLING (period-5 static ring offsets).
//   The 10-slot register ring advances 2/pair -> period 5. The pair body is
//   instantiated 5x with compile-time ring offsets {0,2,4,6,8} in a
//   while(p+5<=npairs) loop (+ <=4 static tail bodies) -> ZERO shift MOVs
//   (was ~72 MOV32/pair under unroll 1). Staging slot parity is static
//   (row i+5 odd -> slot1, i+6 even -> slot0).
//   Everything else = v15: grid (9,48), 128 thr, 4 cols/thread, 3 CTAs/SM;
//   shared-product streamed vertical conv (f32x2, packed weights);
//   cp.async.cg 2-slot staging issued 2 rows ahead; scalar FFMA-imm
//   horizontal from quad-buffered padded smem; ONE barrier per 2 rows;
//   finalize folded into the last block.

#define HH 512
#define WW 512
#define NTHREADS 128
#define NPIX 12582912.0
#define GX 9
#define GY 48
#define NBLOCKS (GX * GY)
#define FULLM 0xFFFFFFFFu

typedef unsigned long long u64;

__device__ constexpr float KW[11] = {
    0.00102839f, 0.00759876f, 0.03600077f, 0.10936069f, 0.21300554f,
    0.26601172f,
    0.21300554f, 0.10936069f, 0.03600077f, 0.00759876f, 0.00102839f};

__device__ double g_partial[NBLOCKS];
__device__ unsigned g_count = 0;

// ---- f32x2 packed helpers (sm_100+ PTX) ----
__device__ __forceinline__ u64 pk2(float lo, float hi) {
    u64 r; asm("mov.b64 %0, {%1, %2};" : "=l"(r) : "f"(lo), "f"(hi)); return r;
}
__device__ __forceinline__ u64 f2mul(u64 a, u64 b) {
    u64 r; asm("mul.rn.f32x2 %0, %1, %2;" : "=l"(r) : "l"(a), "l"(b)); return r;
}
__device__ __forceinline__ u64 f2fma(u64 a, u64 b, u64 c) {
    u64 r; asm("fma.rn.f32x2 %0, %1, %2, %3;" : "=l"(r) : "l"(a), "l"(b), "l"(c));
    return r;
}

// ---- cp.async helpers ----
__device__ __forceinline__ void cp16(unsigned dst, const float* src) {
    asm volatile("cp.async.cg.shared.global [%0], [%1], 16;"
                 :: "r"(dst), "l"(src));
}
#define CP_COMMIT() asm volatile("cp.async.commit_group;" ::: "memory")
#define CP_WAIT1()  asm volatile("cp.async.wait_group 1;" ::: "memory")

__device__ __forceinline__ void load_row_pk(const float* __restrict__ base,
                                            int row, int c0, u64 o[2]) {
    if ((unsigned)row < (unsigned)HH) {
        ulonglong2 v = *reinterpret_cast<const ulonglong2*>(
            base + (size_t)row * WW + c0);
        o[0] = v.x;
        o[1] = v.y;
    } else {
        o[0] = 0ull; o[1] = 0ull;
    }
}

// ---- pair body: 2 output rows, compile-time ring offset ROFF ----
// Ring invariant on entry: rga[(k+ROFF)%10] = source row (i-5+k), k=0..9.
// On exit: rows i+5, i+6 written into slots (ROFF)%10, (ROFF+1)%10,
// establishing the invariant for ROFF+2.
#define PAIR_BODY(P, ROFF)                                                     \
{                                                                              \
    const int bufA_ = ((P) & 1) * 2;                                           \
    const int bufB_ = bufA_ + 1;                                               \
    const int i_ = r0 + 2 * (P);                                               \
    u64 st5a[2], st5b[2], st6a[2], st6b[2];                                    \
    {                                                                          \
        const int g5 = i_ + 5, g6 = i_ + 6; /* g5 odd->slot1, g6 even->slot0*/ \
        CP_WAIT1();                                                            \
        ulonglong2 ta = *reinterpret_cast<const ulonglong2*>(&stageA[1][c0]);  \
        ulonglong2 tb = *reinterpret_cast<const ulonglong2*>(&stageB[1][c0]);  \
        if (g5 >= HH) { ta.x = 0; ta.y = 0; tb.x = 0; tb.y = 0; }              \
        st5a[0] = ta.x; st5a[1] = ta.y; st5b[0] = tb.x; st5b[1] = tb.y;        \
        { int rc = (g5 + 2 < HH) ? (g5 + 2) : (HH - 1);                        \
          cp16(sA[1], pa0 + (size_t)rc * WW);                                  \
          cp16(sB[1], pb0 + (size_t)rc * WW); CP_COMMIT(); }                   \
        CP_WAIT1();                                                            \
        ta = *reinterpret_cast<const ulonglong2*>(&stageA[0][c0]);             \
        tb = *reinterpret_cast<const ulonglong2*>(&stageB[0][c0]);             \
        if (g6 >= HH) { ta.x = 0; ta.y = 0; tb.x = 0; tb.y = 0; }              \
        st6a[0] = ta.x; st6a[1] = ta.y; st6b[0] = tb.x; st6b[1] = tb.y;        \
        { int rc = (g6 + 2 < HH) ? (g6 + 2) : (HH - 1);                        \
          cp16(sA[0], pa0 + (size_t)rc * WW);                                  \
          cp16(sB[0], pb0 + (size_t)rc * WW); CP_COMMIT(); }                   \
    }                                                                          \
    u64 A[4][2], B[4][2];                                                      \
    _Pragma("unroll")                                                          \
    for (int s = 0; s < 12; ++s) {                                             \
        _Pragma("unroll")                                                      \
        for (int q = 0; q < 2; ++q) {                                          \
            u64 a, b;                                                          \
            if (s < 10)       { a = rga[(s + (ROFF)) % 10][q];                 \
                                b = rgb[(s + (ROFF)) % 10][q]; }               \
            else if (s == 10) { a = st5a[q]; b = st5b[q]; }                    \
            else              { a = st6a[q]; b = st6b[q]; }                    \
            u64 qrow = f2fma(b, b, f2mul(a, a));                               \
            u64 ab = f2mul(a, b);                                              \
            if (s <= 10) {                                                     \
                const int wi = (s <= 5) ? s : (10 - s);                        \
                if (s == 0) {                                                  \
                    A[0][q] = f2mul(WKP[wi], a);                               \
                    A[1][q] = f2mul(WKP[wi], b);                               \
                    A[2][q] = f2mul(WKP[wi], qrow);                            \
                    A[3][q] = f2mul(WKP[wi], ab);                              \
                } else {                                                       \
                    A[0][q] = f2fma(WKP[wi], a, A[0][q]);                      \
                    A[1][q] = f2fma(WKP[wi], b, A[1][q]);                      \
                    A[2][q] = f2fma(WKP[wi], qrow, A[2][q]);                   \
                    A[3][q] = f2fma(WKP[wi], ab, A[3][q]);                     \
                }                                                              \
            }                                                                  \
            if (s >= 1) {                                                      \
                const int k1 = s - 1;                                          \
                const int wi = (k1 <= 5) ? k1 : (10 - k1);                     \
                if (s == 1) {                                                  \
                    B[0][q] = f2mul(WKP[wi], a);                               \
                    B[1][q] = f2mul(WKP[wi], b);                               \
                    B[2][q] = f2mul(WKP[wi], qrow);                            \
                    B[3][q] = f2mul(WKP[wi], ab);                              \
                } else {                                                       \
                    B[0][q] = f2fma(WKP[wi], a, B[0][q]);                      \
                    B[1][q] = f2fma(WKP[wi], b, B[1][q]);                      \
                    B[2][q] = f2fma(WKP[wi], qrow, B[2][q]);                   \
                    B[3][q] = f2fma(WKP[wi], ab, B[3][q]);                     \
                }                                                              \
            }                                                                  \
        }                                                                      \
    }                                                                          \
    _Pragma("unroll")                                                          \
    for (int f = 0; f < 4; ++f) {                                              \
        *reinterpret_cast<ulonglong2*>(&vsbuf[bufA_][f][8 + c0]) =             \
            make_ulonglong2(A[f][0], A[f][1]);                                 \
        *reinterpret_cast<ulonglong2*>(&vsbuf[bufB_][f][8 + c0]) =             \
            make_ulonglong2(B[f][0], B[f][1]);                                 \
    }                                                                          \
    _Pragma("unroll")                                                          \
    for (int q = 0; q < 2; ++q) {                                              \
        rga[(ROFF) % 10][q] = st5a[q];       rgb[(ROFF) % 10][q] = st5b[q];    \
        rga[((ROFF) + 1) % 10][q] = st6a[q]; rgb[((ROFF) + 1) % 10][q] = st6b[q];\
    }                                                                          \
    __syncthreads();                                                           \
    _Pragma("unroll")                                                          \
    for (int r = 0; r < 2; ++r) {                                              \
        const int buf = bufA_ + r;                                             \
        float cv[4][4];                                                        \
        _Pragma("unroll")                                                      \
        for (int f = 0; f < 4; ++f) {                                          \
            float v[20];                                                       \
            _Pragma("unroll")                                                  \
            for (int q5 = 0; q5 < 5; ++q5) {                                   \
                float4 t = *reinterpret_cast<const float4*>(                   \
                    &vsbuf[buf][f][c0 + 4 * q5]);                              \
                v[4 * q5 + 0] = t.x; v[4 * q5 + 1] = t.y;                      \
                v[4 * q5 + 2] = t.z; v[4 * q5 + 3] = t.w;                      \
            }                                                                  \
            _Pragma("unroll")                                                  \
            for (int j = 0; j < 4; ++j) {                                      \
                float s = KW[5] * v[8 + j];                                    \
                _Pragma("unroll")                                              \
                for (int k = 0; k < 11; ++k) {                                 \
                    if (k == 5) continue;                                      \
                    s += KW[k] * v[3 + j + k];                                 \
                }                                                              \
                cv[f][j] = s;                                                  \
            }                                                                  \
        }                                                                      \
        _Pragma("unroll")                                                      \
        for (int j = 0; j < 4; ++j) {                                          \
            float m1 = cv[0][j], m2 = cv[1][j];                                \
            float qv = cv[2][j], pv = cv[3][j];                                \
            float m12 = m1 * m2;                                               \
            float sms = fmaf(m1, m1, m2 * m2);                                 \
            float num1 = fmaf(m12, 2.f, 1e-4f);                                \
            float num2 = fmaf(pv - m12, 2.f, 9e-4f);                           \
            float den1 = sms + 1e-4f;                                          \
            float den2 = (qv - sms) + 9e-4f;                                   \
            acc += __fdividef(num1 * num2, den1 * den2);                       \
        }                                                                      \
    }                                                                          \
}

__global__ __launch_bounds__(NTHREADS, 3)
void ssim_kernel(const float* __restrict__ sr, const float* __restrict__ hr,
                 float* __restrict__ out) {
    const int plane = blockIdx.y;
    const int bx = blockIdx.x;
    // chunks: 58,58,58,58,56,56,56,56,56 (all even; sum = 512)
    const int r0 = (bx < 4) ? 58 * bx : (232 + 56 * (bx - 4));
    const int npairs = (bx < 4) ? 29 : 28;
    const int tid = threadIdx.x;
    const int c0 = tid * 4;

    const float* __restrict__ pa0 = sr + (size_t)plane * HH * WW + c0;
    const float* __restrict__ pb0 = hr + (size_t)plane * HH * WW + c0;

    __shared__ __align__(16) float vsbuf[4][4][528];
    __shared__ __align__(16) float stageA[2][WW];
    __shared__ __align__(16) float stageB[2][WW];

    {
        for (int q = tid; q < 256; q += NTHREADS) {
            int b = q >> 6;
            int f = (q >> 4) & 3;
            int k = q & 15;
            int idx = (k < 8) ? k : (512 + k);
            vsbuf[b][f][idx] = 0.f;
        }
    }
    __syncthreads();

    unsigned sA[2], sB[2];
#pragma unroll
    for (int s = 0; s < 2; ++s) {
        sA[s] = (unsigned)__cvta_generic_to_shared(&stageA[s][c0]);
        sB[s] = (unsigned)__cvta_generic_to_shared(&stageB[s][c0]);
    }

    u64 WKP[6];
#pragma unroll
    for (int k = 0; k < 6; ++k) WKP[k] = pk2(KW[k], KW[k]);

    // Register ring: slot k holds source row (r0-5+k), k=0..9 (ROFF=0).
    u64 rga[10][2], rgb[10][2];
#pragma unroll
    for (int k = 0; k < 10; ++k) {
        load_row_pk(pa0 - c0, r0 - 5 + k, c0, rga[k]);
        load_row_pk(pb0 - c0, r0 - 5 + k, c0, rgb[k]);
    }

    // Prologue staging: rows r0+5 (odd -> slot 1), r0+6 (even -> slot 0).
    {
        int g5 = r0 + 5, g6 = r0 + 6;
        cp16(sA[1], pa0 + (size_t)g5 * WW);
        cp16(sB[1], pb0 + (size_t)g5 * WW);
        CP_COMMIT();
        cp16(sA[0], pa0 + (size_t)g6 * WW);
        cp16(sB[0], pb0 + (size_t)g6 * WW);
        CP_COMMIT();
    }

    float acc = 0.f;

    int p = 0;
    while (p + 5 <= npairs) {
        PAIR_BODY(p + 0, 0)
        PAIR_BODY(p + 1, 2)
        PAIR_BODY(p + 2, 4)
        PAIR_BODY(p + 3, 6)
        PAIR_BODY(p + 4, 8)
        p += 5;
    }
    // tail (<= 4 pairs; ring offset continues from 0)
    if (p < npairs) { PAIR_BODY(p, 0) ++p; }
    if (p < npairs) { PAIR_BODY(p, 2) ++p; }
    if (p < npairs) { PAIR_BODY(p, 4) ++p; }
    if (p < npairs) { PAIR_BODY(p, 6) ++p; }

    // block reduction -> per-block partial
#pragma unroll
    for (int o = 16; o > 0; o >>= 1)
        acc += __shfl_down_sync(FULLM, acc, o);

    __shared__ float wsum[4];
    __shared__ int is_last;
    if ((tid & 31) == 0) wsum[tid >> 5] = acc;
    __syncthreads();
    if (tid == 0) {
        double s = (double)wsum[0] + (double)wsum[1] + (double)wsum[2] +
                   (double)wsum[3];
        g_partial[blockIdx.y * GX + blockIdx.x] = s;
        __threadfence();
        unsigned old = atomicInc(&g_count, NBLOCKS - 1);  // wraps to 0
        is_last = (old == NBLOCKS - 1);
    }
    __syncthreads();

    // last block finalizes (replay-deterministic: counter wraps to 0)
    if (is_last) {
        __threadfence();
        double s = 0.0;
        for (int i2 = tid; i2 < NBLOCKS; i2 += NTHREADS)
            s += __ldcg(&g_partial[i2]);
#pragma unroll
        for (int o = 16; o > 0; o >>= 1)
            s += __shfl_down_sync(FULLM, s, o);
        __shared__ double dsm[4];
        if ((tid & 31) == 0) dsm[tid >> 5] = s;
        __syncthreads();
        if (tid == 0) {
            double tot = dsm[0] + dsm[1] + dsm[2] + dsm[3];
            out[0] = (float)(1.0 - tot / NPIX);
        }
    }
}

extern "C" void kernel_launch(void* const* d_in, const int* in_sizes, int n_in,
                              void* d_out, int out_size) {
    const float* sr = (const float*)d_in[0];
    const float* hr = (const float*)d_in[1];
    float* out = (float*)d_out;

    dim3 grid(GX, GY);
    ssim_kernel<<<grid, NTHREADS>>>(sr, hr, out);
}

// round 17
// speedup vs baseline: 1.1827x; 1.1827x over previous
#include <cuda_runtime.h>

// SSIM loss, fused separable 11x11 Gaussian, B=16 C=3 H=512 W=512 fp32.
// v17 = v15 + ROW-PAIR PACKED horizontal conv on a pad-per-4 u64 smem
//   layout (conflict-free by construction: u64 idx g(L)=L+(L>>2) puts lane
//   t's 8-byte accesses at banks 10t mod 32 -> 16 distinct even residues
//   per 16-lane phase).
//   Per pair (2 output rows): column-packed vertical conv (unchanged from
//   v15: shared-product streamed over 12 source rows, f2 math, packed
//   weights), then a 32-MOV register transpose packs (rowA,rowB) per column
//   per field into u64; publish 16 STS.64; horizontal conv runs PACKED:
//   own 4 cols from registers + 10 halo LDS.64 per field, 11 f2fma per
//   output -> 176 packed slots vs 352 scalar. Single vsbuf (21KB), two
//   __syncthreads per pair. Everything else = v15 (grid 9x48, 128 thr,
//   3 CTAs/SM, cp.async 2-slot staging, unroll 1, last-block finalize).

#define HH 512
#define WW 512
#define NTHREADS 128
#define NPIX 12582912.0
#define GX 9
#define GY 48
#define NBLOCKS (GX * GY)
#define FULLM 0xFFFFFFFFu

typedef unsigned long long u64;

__device__ constexpr float KW[11] = {
    0.00102839f, 0.00759876f, 0.03600077f, 0.10936069f, 0.21300554f,
    0.26601172f,
    0.21300554f, 0.10936069f, 0.03600077f, 0.00759876f, 0.00102839f};

__device__ double g_partial[NBLOCKS];
__device__ unsigned g_count = 0;

// ---- f32x2 packed helpers (sm_100+ PTX) ----
__device__ __forceinline__ u64 pk2(float lo, float hi) {
    u64 r; asm("mov.b64 %0, {%1, %2};" : "=l"(r) : "f"(lo), "f"(hi)); return r;
}
__device__ __forceinline__ void upk2(u64 v, float& lo, float& hi) {
    asm("mov.b64 {%0, %1}, %2;" : "=f"(lo), "=f"(hi) : "l"(v));
}
__device__ __forceinline__ u64 f2mul(u64 a, u64 b) {
    u64 r; asm("mul.rn.f32x2 %0, %1, %2;" : "=l"(r) : "l"(a), "l"(b)); return r;
}
__device__ __forceinline__ u64 f2fma(u64 a, u64 b, u64 c) {
    u64 r; asm("fma.rn.f32x2 %0, %1, %2, %3;" : "=l"(r) : "l"(a), "l"(b), "l"(c));
    return r;
}

// ---- cp.async helpers ----
__device__ __forceinline__ void cp16(unsigned dst, const float* src) {
    asm volatile("cp.async.cg.shared.global [%0], [%1], 16;"
                 :: "r"(dst), "l"(src));
}
#define CP_COMMIT() asm volatile("cp.async.commit_group;" ::: "memory")
#define CP_WAIT1()  asm volatile("cp.async.wait_group 1;" ::: "memory")

__device__ __forceinline__ void load_row_pk(const float* __restrict__ base,
                                            int row, int c0, u64 o[2]) {
    if ((unsigned)row < (unsigned)HH) {
        ulonglong2 v = *reinterpret_cast<const ulonglong2*>(
            base + (size_t)row * WW + c0);
        o[0] = v.x;
        o[1] = v.y;
    } else {
        o[0] = 0ull; o[1] = 0ull;
    }
}

// padded u64 index: data col c (in [-8, 519]) -> L = c+8 -> g = L + (L>>2)
__device__ __forceinline__ int gidx(int L) { return L + (L >> 2); }

#define VSN 656  // g(524)=655 max

__global__ __launch_bounds__(NTHREADS, 3)
void ssim_kernel(const float* __restrict__ sr, const float* __restrict__ hr,
                 float* __restrict__ out) {
    const int plane = blockIdx.y;
    const int bx = blockIdx.x;
    // chunks: 58,58,58,58,56,56,56,56,56 (all even; sum = 512)
    const int r0 = (bx < 4) ? 58 * bx : (232 + 56 * (bx - 4));
    const int npairs = (bx < 4) ? 29 : 28;
    const int tid = threadIdx.x;
    const int c0 = tid * 4;

    const float* __restrict__ pa0 = sr + (size_t)plane * HH * WW + c0;
    const float* __restrict__ pb0 = hr + (size_t)plane * HH * WW + c0;

    // Single padded line buffer: [field][g] u64 = (rowA, rowB) packed.
    __shared__ __align__(16) u64 vs2[4][VSN];
    // cp.async staging: 2 slots (by incoming-row parity) x 2 tensors.
    __shared__ __align__(16) float stageA[2][WW];
    __shared__ __align__(16) float stageB[2][WW];

    // zero halos: cols -5..-1 (L=3..7) and 512..516 (L=520..524), 4 fields
    {
        for (int q = tid; q < 40; q += NTHREADS) {
            int f = q / 10;
            int m = q % 10;
            int L = (m < 5) ? (3 + m) : (515 + m);
            vs2[f][gidx(L)] = 0ull;
        }
    }
    __syncthreads();

    unsigned sA[2], sB[2];
#pragma unroll
    for (int s = 0; s < 2; ++s) {
        sA[s] = (unsigned)__cvta_generic_to_shared(&stageA[s][c0]);
        sB[s] = (unsigned)__cvta_generic_to_shared(&stageB[s][c0]);
    }

    // Packed weight constants (symmetric kernel -> 6 uniques).
    u64 WKP[6];
#pragma unroll
    for (int k = 0; k < 6; ++k) WKP[k] = pk2(KW[k], KW[k]);

    // Register ring: positions 0..9 hold source rows (i-5) .. (i+4).
    u64 rga[10][2], rgb[10][2];
#pragma unroll
    for (int k = 0; k < 10; ++k) {
        load_row_pk(pa0 - c0, r0 - 5 + k, c0, rga[k]);
        load_row_pk(pb0 - c0, r0 - 5 + k, c0, rgb[k]);
    }

    // Prologue staging: rows r0+5, r0+6 (both < HH since r0 <= 456).
    {
        int g5 = r0 + 5, g6 = r0 + 6;
        cp16(sA[g5 & 1], pa0 + (size_t)g5 * WW);
        cp16(sB[g5 & 1], pb0 + (size_t)g5 * WW);
        CP_COMMIT();
        cp16(sA[g6 & 1], pa0 + (size_t)g6 * WW);
        cp16(sB[g6 & 1], pb0 + (size_t)g6 * WW);
        CP_COMMIT();
    }

    float acc = 0.f;

#pragma unroll 1
    for (int p = 0; p < npairs; ++p) {
        const int i = r0 + 2 * p;

        // ---- consume staged rows i+5, i+6; refill slots with i+7, i+8 ----
        u64 st5a[2], st5b[2], st6a[2], st6b[2];
        {
            const int g5 = i + 5, g6 = i + 6;
            const int sl5 = g5 & 1, sl6 = g6 & 1;

            CP_WAIT1();  // row g5 complete
            ulonglong2 ta = *reinterpret_cast<const ulonglong2*>(&stageA[sl5][c0]);
            ulonglong2 tb = *reinterpret_cast<const ulonglong2*>(&stageB[sl5][c0]);
            if (g5 >= HH) { ta.x = 0; ta.y = 0; tb.x = 0; tb.y = 0; }
            st5a[0] = ta.x; st5a[1] = ta.y; st5b[0] = tb.x; st5b[1] = tb.y;
            {
                int rc = (g5 + 2 < HH) ? (g5 + 2) : (HH - 1);
                cp16(sA[sl5], pa0 + (size_t)rc * WW);
                cp16(sB[sl5], pb0 + (size_t)rc * WW);
                CP_COMMIT();
            }

            CP_WAIT1();  // row g6 complete
            ta = *reinterpret_cast<const ulonglong2*>(&stageA[sl6][c0]);
            tb = *reinterpret_cast<const ulonglong2*>(&stageB[sl6][c0]);
            if (g6 >= HH) { ta.x = 0; ta.y = 0; tb.x = 0; tb.y = 0; }
            st6a[0] = ta.x; st6a[1] = ta.y; st6b[0] = tb.x; st6b[1] = tb.y;
            {
                int rc = (g6 + 2 < HH) ? (g6 + 2) : (HH - 1);
                cp16(sA[sl6], pa0 + (size_t)rc * WW);
                cp16(sB[sl6], pb0 + (size_t)rc * WW);
                CP_COMMIT();
            }
        }

        // ---- vertical conv streamed over 12 source rows (column-packed) ----
        // A = output row i (taps s=0..10, KW[s]); B = row i+1 (s=1..11).
        // fields: 0=mu1, 1=mu2, 2=q(a^2+b^2), 3=p(ab)
        u64 A[4][2], B[4][2];
#pragma unroll
        for (int s = 0; s < 12; ++s) {
#pragma unroll
            for (int q = 0; q < 2; ++q) {
                u64 a, b;
                if (s < 10)      { a = rga[s][q]; b = rgb[s][q]; }
                else if (s == 10){ a = st5a[q];   b = st5b[q]; }
                else             { a = st6a[q];   b = st6b[q]; }
                u64 qrow = f2fma(b, b, f2mul(a, a));
                u64 ab = f2mul(a, b);
                if (s <= 10) {
                    const int wi = (s <= 5) ? s : (10 - s);
                    if (s == 0) {
                        A[0][q] = f2mul(WKP[wi], a);
                        A[1][q] = f2mul(WKP[wi], b);
                        A[2][q] = f2mul(WKP[wi], qrow);
                        A[3][q] = f2mul(WKP[wi], ab);
                    } else {
                        A[0][q] = f2fma(WKP[wi], a, A[0][q]);
                        A[1][q] = f2fma(WKP[wi], b, A[1][q]);
                        A[2][q] = f2fma(WKP[wi], qrow, A[2][q]);
                        A[3][q] = f2fma(WKP[wi], ab, A[3][q]);
                    }
                }
                if (s >= 1) {
                    const int k1 = s - 1;
                    const int wi = (k1 <= 5) ? k1 : (10 - k1);
                    if (s == 1) {
                        B[0][q] = f2mul(WKP[wi], a);
                        B[1][q] = f2mul(WKP[wi], b);
                        B[2][q] = f2mul(WKP[wi], qrow);
                        B[3][q] = f2mul(WKP[wi], ab);
                    } else {
                        B[0][q] = f2fma(WKP[wi], a, B[0][q]);
                        B[1][q] = f2fma(WKP[wi], b, B[1][q]);
                        B[2][q] = f2fma(WKP[wi], qrow, B[2][q]);
                        B[3][q] = f2fma(WKP[wi], ab, B[3][q]);
                    }
                }
            }
        }

        // ---- transpose to row-pair packs + publish (STS.64, padded) ----
        // own[f][j] = (rowA col c0+j, rowB col c0+j)
        u64 own[4][4];
#pragma unroll
        for (int f = 0; f < 4; ++f) {
            float a0, a1, a2, a3, b0, b1, b2, b3;
            upk2(A[f][0], a0, a1);
            upk2(A[f][1], a2, a3);
            upk2(B[f][0], b0, b1);
            upk2(B[f][1], b2, b3);
            own[f][0] = pk2(a0, b0);
            own[f][1] = pk2(a1, b1);
            own[f][2] = pk2(a2, b2);
            own[f][3] = pk2(a3, b3);
#pragma unroll
            for (int j = 0; j < 4; ++j)
                vs2[f][gidx(c0 + 8 + j)] = own[f][j];
        }

        // advance ring by 2 rows; staged rows enter the ring
#pragma unroll
        for (int k = 0; k < 8; ++k) {
#pragma unroll
            for (int q = 0; q < 2; ++q) {
                rga[k][q] = rga[k + 2][q];
                rgb[k][q] = rgb[k + 2][q];
            }
        }
#pragma unroll
        for (int q = 0; q < 2; ++q) {
            rga[8][q] = st5a[q]; rgb[8][q] = st5b[q];
            rga[9][q] = st6a[q]; rgb[9][q] = st6b[q];
        }

        __syncthreads();  // publish visible

        // ---- PACKED horizontal conv + scalar map, both rows at once ----
#pragma unroll
        for (int f = 0; f < 4; ++f) {
            // window w[m] = col c0-5+m, m=0..13 (u64 = (rowA,rowB))
            u64 w[14];
#pragma unroll
            for (int m = 0; m < 5; ++m)
                w[m] = vs2[f][gidx(c0 + 3 + m)];       // left halo
#pragma unroll
            for (int j = 0; j < 4; ++j)
                w[5 + j] = own[f][j];                  // own cols (regs)
#pragma unroll
            for (int m = 0; m < 5; ++m)
                w[9 + m] = vs2[f][gidx(c0 + 12 + m)];  // right halo
#pragma unroll
            for (int j = 0; j < 4; ++j) {
                u64 s = f2mul(WKP[5], w[j + 5]);
#pragma unroll
                for (int k = 0; k < 11; ++k) {
                    if (k == 5) continue;
                    const int wi = (k < 5) ? k : (10 - k);
                    s = f2fma(WKP[wi], w[j + k], s);
                }
                own[f][j] = s;  // reuse own[] as cv output (A,B packed)
            }
        }

        // scalar SSIM map: 4 cols x 2 rows
#pragma unroll
        for (int j = 0; j < 4; ++j) {
            float m1A, m1B, m2A, m2B, qA, qB, pA, pB;
            upk2(own[0][j], m1A, m1B);
            upk2(own[1][j], m2A, m2B);
            upk2(own[2][j], qA, qB);
            upk2(own[3][j], pA, pB);
            {
                float m12 = m1A * m2A;
                float sms = fmaf(m1A, m1A, m2A * m2A);
                float num1 = fmaf(m12, 2.f, 1e-4f);
                float num2 = fmaf(pA - m12, 2.f, 9e-4f);
                float den1 = sms + 1e-4f;
                float den2 = (qA - sms) + 9e-4f;
                acc += __fdividef(num1 * num2, den1 * den2);
            }
            {
                float m12 = m1B * m2B;
                float sms = fmaf(m1B, m1B, m2B * m2B);
                float num1 = fmaf(m12, 2.f, 1e-4f);
                float num2 = fmaf(pB - m12, 2.f, 9e-4f);
                float den1 = sms + 1e-4f;
                float den2 = (qB - sms) + 9e-4f;
                acc += __fdividef(num1 * num2, den1 * den2);
            }
        }

        __syncthreads();  // reads done before next pair's writes
    }

    // block reduction -> per-block partial
#pragma unroll
    for (int o = 16; o > 0; o >>= 1)
        acc += __shfl_down_sync(FULLM, acc, o);

    __shared__ float wsum[4];
    __shared__ int is_last;
    if ((tid & 31) == 0) wsum[tid >> 5] = acc;
    __syncthreads();
    if (tid == 0) {
        double s = (double)wsum[0] + (double)wsum[1] + (double)wsum[2] +
                   (double)wsum[3];
        g_partial[blockIdx.y * GX + blockIdx.x] = s;
        __threadfence();
        unsigned old = atomicInc(&g_count, NBLOCKS - 1);  // wraps to 0
        is_last = (old == NBLOCKS - 1);
    }
    __syncthreads();

    // last block finalizes (replay-deterministic: counter wraps to 0)
    if (is_last) {
        __threadfence();
        double s = 0.0;
        for (int i2 = tid; i2 < NBLOCKS; i2 += NTHREADS)
            s += __ldcg(&g_partial[i2]);
#pragma unroll
        for (int o = 16; o > 0; o >>= 1)
            s += __shfl_down_sync(FULLM, s, o);
        __shared__ double dsm[4];
        if ((tid & 31) == 0) dsm[tid >> 5] = s;
        __syncthreads();
        if (tid == 0) {
            double tot = dsm[0] + dsm[1] + dsm[2] + dsm[3];
            out[0] = (float)(1.0 - tot / NPIX);
        }
    }
}

extern "C" void kernel_launch(void* const* d_in, const int* in_sizes, int n_in,
                              void* d_out, int out_size) {
    const float* sr = (const float*)d_in[0];
    const float* hr = (const float*)d_in[1];
    float* out = (float*)d_out;

    dim3 grid(GX, GY);
    ssim_kernel<<<grid, NTHREADS>>>(sr, hr, out);
}